// round 5
// baseline (speedup 1.0000x reference)
#include <cuda_runtime.h>
#include <stdint.h>

#define H 2048
#define W 2048
#define KS 11
#define PS 10
#define PAD 5
#define HO 205                 // conv output: floor((2048+10-11)/10)+1
#define OUT 2255               // 205 * (PS+1)
#define CELLS (HO*HO)
#define GROUPS (3*HO)          // (channel, oh) bands

// Intermediate per-cell result: [3][HO][HO] (+pad for safe m1 over-read)
__device__ float g_mid[3 * HO * HO + 8];

// ---------------------------------------------------------------------------
// Kernel 1: one warp per output cell.
// 16-bin histogram of the 11x11 window (packed 8-bit counters), argmax bin
// via single warp-reduce-max (first-max tie-break like jnp.argmax),
// per-channel mean of pixels in that bin.
// ---------------------------------------------------------------------------
__global__ void __launch_bounds__(256) cell_kernel(const float* __restrict__ rgb) {
    const int wid = (blockIdx.x * blockDim.x + threadIdx.x) >> 5;
    if (wid >= CELLS) return;
    const int lane = threadIdx.x & 31;

    const int oh = wid / HO;
    const int ow = wid - oh * HO;
    const int y0 = oh * PS - PAD;
    const int x0 = ow * PS - PAD;

    const float* __restrict__ rp = rgb;
    const float* __restrict__ gp = rgb + H * W;
    const float* __restrict__ bp = rgb + 2 * H * W;

    // p = lane + 32t; window is 121 px: t=0..2 always active, t=3 iff lane<25.
    int off[4];
    bool act[4];
    act[0] = true; act[1] = true; act[2] = true; act[3] = (lane < 25);
#pragma unroll
    for (int t = 0; t < 4; t++) {
        const int p = lane + t * 32;
        const int dy = p / KS;
        const int dx = p - dy * KS;
        off[t] = (y0 + dy) * W + (x0 + dx);
    }
    if ((oh == 0) | (ow == 0)) {   // border cells: 409 of 42025
#pragma unroll
        for (int t = 0; t < 4; t++) {
            const int p = lane + t * 32;
            const int dy = p / KS;
            const int dx = p - dy * KS;
            act[t] = act[t] && (y0 + dy >= 0) && (x0 + dx >= 0);
        }
    }

    // Batch all loads first (max MLP); inactive slots hold 0.
    float rv[4], gv[4], bv[4];
#pragma unroll
    for (int t = 0; t < 4; t++) rv[t] = act[t] ? __ldg(rp + off[t]) : 0.0f;
#pragma unroll
    for (int t = 0; t < 4; t++) gv[t] = act[t] ? __ldg(gp + off[t]) : 0.0f;
#pragma unroll
    for (int t = 0; t < 4; t++) bv[t] = act[t] ? __ldg(bp + off[t]) : 0.0f;

    // Bin + packed histogram (bins 0-7 in hlo, 8-15 in hhi; 8-bit counters,
    // per-bin totals <= 121 < 256 so the warp reduction is carry-free)
    int bn[4];
    unsigned long long hlo = 0ULL, hhi = 0ULL;
#pragma unroll
    for (int t = 0; t < 4; t++) {
        // bin = floor(mean(r,g,b)/256*16) = floor((r+g+b)*(1/3)*2^-4)
        const float s = __fadd_rn(__fadd_rn(rv[t], gv[t]), bv[t]);
        const float m = __fmul_rn(s, 0.3333333432674408f);   // 1/3 rn
        const int bi = (int)(__fmul_rn(m, 0.0625f));          // in [0,15]
        bn[t] = bi;
        if (act[t]) {
            const unsigned long long inc = 1ULL << ((bi & 7) * 8);
            if (bi < 8) hlo += inc; else hhi += inc;
        }
    }

    const unsigned h0 = __reduce_add_sync(0xffffffffu, (unsigned)hlo);
    const unsigned h1 = __reduce_add_sync(0xffffffffu, (unsigned)(hlo >> 32));
    const unsigned h2 = __reduce_add_sync(0xffffffffu, (unsigned)hhi);
    const unsigned h3 = __reduce_add_sync(0xffffffffu, (unsigned)(hhi >> 32));

    // Lane-parallel argmax: lane (b = lane&15) owns bin b.
    // key = (cnt<<4) | (15-b): ties -> larger 15-b -> smaller bin wins,
    // matching jnp.argmax first-max semantics.
    const int b = lane & 15;
    const unsigned hw = (b < 8) ? ((b < 4) ? h0 : h1) : ((b < 12) ? h2 : h3);
    const unsigned cnt = (hw >> ((b & 3) * 8)) & 0xFFu;
    const unsigned key = (cnt << 4) | (unsigned)(15 - b);
    const unsigned kmax = __reduce_max_sync(0xffffffffu, key);
    const int amax = 15 - (int)(kmax & 15u);
    const float cm = (float)(kmax >> 4);

    // Masked per-channel sums (inactive slots hold 0.0)
    float sr = 0.f, sg = 0.f, sb = 0.f;
#pragma unroll
    for (int t = 0; t < 4; t++) {
        if (bn[t] == amax) { sr += rv[t]; sg += gv[t]; sb += bv[t]; }
    }
#pragma unroll
    for (int s = 16; s > 0; s >>= 1) {
        sr += __shfl_xor_sync(0xffffffffu, sr, s);
        sg += __shfl_xor_sync(0xffffffffu, sg, s);
        sb += __shfl_xor_sync(0xffffffffu, sb, s);
    }

    if (lane == 0) {
        const float inv = __frcp_rn(cm);   // 1 rcp + 3 muls instead of 3 divs
        g_mid[wid]               = __fmul_rn(sr, inv);
        g_mid[wid + HO * HO]     = __fmul_rn(sg, inv);
        g_mid[wid + 2 * HO * HO] = __fmul_rn(sb, inv);
    }
}

// ---------------------------------------------------------------------------
// Kernel 2: upsample. One thread per (band, float4-column). The 10 live rows
// of a band are identical: compute the float4 once (4 alignment phases from
// 7 shifted elements) and store to all 11 rows (pad row gets zeros).
// Row length 2255 == 3 (mod 4) so the alignment phase of row r is (h0+r)&3;
// rows sharing a phase share one register float4 -> all stores are STG.128.
// ---------------------------------------------------------------------------
__global__ void __launch_bounds__(192) upsample_kernel(float* __restrict__ out) {
    const int g = blockIdx.y;                      // 0 .. 3*205-1
    const int v = blockIdx.x * 192 + threadIdx.x;  // float4-column id
    const unsigned c = (unsigned)g / 205u;
    const int oh = g - (int)c * 205;

    const float* __restrict__ midc = g_mid + c * (HO * HO) + (unsigned)oh * HO;
    const unsigned base0 = (c * (unsigned)OUT + (unsigned)oh * 11u) * (unsigned)OUT;
    const int h0 = (int)((4u - (base0 & 3u)) & 3u);

    if (v < 563) {
        const unsigned x0 = 4u * (unsigned)v;
        const unsigned ow0 = x0 / 11u;
        const int j0 = (int)(x0 - ow0 * 11u);      // 0..10
        const float m0 = __ldg(midc + ow0);
        const float m1 = __ldg(midc + ow0 + 1);    // may over-read into pad; unused then

        // e[i] = value at column x0+i (i=0..6), j = j0+i <= 16
        float e[7];
#pragma unroll
        for (int i = 0; i < 7; i++) {
            const int j = j0 + i;
            e[i] = (j < 10) ? m0 : ((j == 10) ? 0.0f : m1);
        }

#pragma unroll
        for (int p = 0; p < 4; p++) {              // alignment phase
            const int q = (p - h0) & 3;            // first row with this phase
#pragma unroll
            for (int r0 = 0; r0 < 3; r0++) {
                const int r = q + r0 * 4;
                if (r < 11) {
                    const bool live = (r < 10);
                    float4 w;
                    w.x = live ? e[p]     : 0.0f;
                    w.y = live ? e[p + 1] : 0.0f;
                    w.z = live ? e[p + 2] : 0.0f;
                    w.w = live ? e[p + 3] : 0.0f;
                    *(float4*)(out + base0 + (unsigned)r * (unsigned)OUT
                                  + (unsigned)p + x0) = w;
                }
            }
        }
    } else if (v == 563) {
        // Heads (x < h_r) and tails (x >= h_r + 2252) of every row in the band
        const float m0 = midc[0];
        const float mL = midc[204];
#pragma unroll
        for (int r = 0; r < 11; r++) {
            const int hr = (h0 + r) & 3;
            const bool live = (r < 10);
            float* __restrict__ rowp = out + base0 + (unsigned)r * (unsigned)OUT;
            for (int x = 0; x < hr; x++)            // x<=2: ow=0, j<10
                rowp[x] = live ? m0 : 0.0f;
            for (int x = hr + 2252; x < OUT; x++)   // x in 2252..2254, j=8,9,10
                rowp[x] = (live && x < 2254) ? mL : 0.0f;
        }
    }
}

extern "C" void kernel_launch(void* const* d_in, const int* in_sizes, int n_in,
                              void* d_out, int out_size) {
    const float* rgb = (const float*)d_in[0];
    float* out = (float*)d_out;

    const int blocks1 = (CELLS + 7) / 8;       // one warp per cell, 8/block
    cell_kernel<<<blocks1, 256>>>(rgb);

    dim3 ugrid(3, GROUPS);                     // 3*192=576 threads >= 564 columns
    upsample_kernel<<<ugrid, 192>>>(out);
}